// round 17
// baseline (speedup 1.0000x reference)
#include <cuda_runtime.h>
#include <cuda_fp16.h>
#include <stdint.h>

#define B_   8
#define N_   1024
#define C_   1024
#define HD_  64
#define FF_  4096
#define BH_  128
#define M_   8192
#define KSP  102

// ---------------- scratch ----------------
__device__ __align__(256) __half g_v[(size_t)BH_*N_*HD_];
__device__ __align__(256) float g_x1[(size_t)M_*C_];
__device__ __align__(256) __half g_qh[(size_t)BH_*N_*HD_], g_ql[(size_t)BH_*N_*HD_];
__device__ __align__(256) __half g_k16[(size_t)BH_*N_*HD_];
__device__ __align__(256) __half g_xnh[(size_t)M_*C_],  g_xnl[(size_t)M_*C_];
__device__ __align__(256) __half g_hnh[(size_t)M_*C_],  g_hnl[(size_t)M_*C_];
__device__ __align__(256) __half g_ath[(size_t)M_*C_],  g_atl[(size_t)M_*C_];
__device__ __align__(256) __half g_h1h[(size_t)M_*FF_], g_h1l[(size_t)M_*FF_];
__device__ __align__(256) __half g_qw16[(size_t)3*C_*C_];
__device__ __align__(256) __half g_ow16[(size_t)C_*C_];
__device__ __align__(256) __half g_w116[(size_t)FF_*C_];
__device__ __align__(256) __half g_w216[(size_t)C_*FF_];

// ---------------- helpers ----------------
__device__ __forceinline__ uint32_t s2u(const void* p) {
    uint32_t a;
    asm("{ .reg .u64 t; cvta.to.shared.u64 t, %1; cvt.u32.u64 %0, t; }" : "=r"(a) : "l"(p));
    return a;
}
__device__ __forceinline__ void h16split(float v, __half& h, __half& l) {
    h = __float2half_rn(v);
    l = __float2half_rn(v - __half2float(h));
}
__device__ __forceinline__ void ldsm4(uint32_t* r, uint32_t a) {
    asm volatile("ldmatrix.sync.aligned.m8n8.x4.shared.b16 {%0,%1,%2,%3}, [%4];"
        : "=r"(r[0]), "=r"(r[1]), "=r"(r[2]), "=r"(r[3]) : "r"(a));
}
__device__ __forceinline__ void mma16816h(float* c, const uint32_t* a, const uint32_t* b) {
    asm volatile("mma.sync.aligned.m16n8k16.row.col.f32.f16.f16.f32 "
        "{%0,%1,%2,%3}, {%4,%5,%6,%7}, {%8,%9}, {%0,%1,%2,%3};"
        : "+f"(c[0]), "+f"(c[1]), "+f"(c[2]), "+f"(c[3])
        : "r"(a[0]), "r"(a[1]), "r"(a[2]), "r"(a[3]), "r"(b[0]), "r"(b[1]));
}
#define CP_ASYNC16(s, g) \
    asm volatile("cp.async.cg.shared.global [%0], [%1], 16;" :: "r"(s), "l"(g))
#define CP_COMMIT() asm volatile("cp.async.commit_group;" ::: "memory")
#define CP_WAIT0()  asm volatile("cp.async.wait_group 0;" ::: "memory")
#define CP_WAIT1()  asm volatile("cp.async.wait_group 1;" ::: "memory")
#define CP_WAIT2()  asm volatile("cp.async.wait_group 2;" ::: "memory")

// ---------------- weight conversion ----------------
__global__ void __launch_bounds__(256)
cvt_w2(const float* __restrict__ s0, __half* __restrict__ d0, int n0,
       const float* __restrict__ s1, __half* __restrict__ d1, int n1)
{
    int i = blockIdx.x * 256 + threadIdx.x;
    const float* s; __half* d;
    if (i < n0) { s = s0; d = d0; }
    else { i -= n0; if (i >= n1) return; s = s1; d = d1; }
    float4 v = ((const float4*)s)[i];
    ((__half2*)d)[i*2]   = __floats2half2_rn(v.x, v.y);
    ((__half2*)d)[i*2+1] = __floats2half2_rn(v.z, v.w);
}

// ---------------- LayerNorm -> fp16 hi/lo ----------------
__global__ void __launch_bounds__(256)
ln_f16(const float* __restrict__ x, const float* __restrict__ w,
       const float* __restrict__ b, __half* __restrict__ yh, __half* __restrict__ yl)
{
    __shared__ float red[16];
    int row = blockIdx.x, t = threadIdx.x;
    float4 v = ((const float4*)(x + (size_t)row * 1024))[t];
    float s  = v.x + v.y + v.z + v.w;
    float ss = v.x*v.x + v.y*v.y + v.z*v.z + v.w*v.w;
    #pragma unroll
    for (int o = 16; o; o >>= 1) {
        s  += __shfl_xor_sync(~0u, s, o);
        ss += __shfl_xor_sync(~0u, ss, o);
    }
    if ((t & 31) == 0) { red[t>>5] = s; red[(t>>5)+8] = ss; }
    __syncthreads();
    if (t == 0) {
        float ts=0.f, tss=0.f;
        #pragma unroll
        for (int i = 0; i < 8; ++i) { ts += red[i]; tss += red[i+8]; }
        float mu = ts * (1.f/1024.f);
        red[0] = mu; red[1] = rsqrtf(tss*(1.f/1024.f) - mu*mu + 1e-5f);
    }
    __syncthreads();
    float mu = red[0], rs = red[1];
    float4 wv = ((const float4*)w)[t];
    float4 bv = ((const float4*)b)[t];
    float o0 = (v.x-mu)*rs*wv.x + bv.x, o1 = (v.y-mu)*rs*wv.y + bv.y;
    float o2 = (v.z-mu)*rs*wv.z + bv.z, o3 = (v.w-mu)*rs*wv.w + bv.w;
    __half h0,h1,h2,h3,l0,l1,l2,l3;
    h16split(o0,h0,l0); h16split(o1,h1,l1); h16split(o2,h2,l2); h16split(o3,h3,l3);
    size_t oi = ((size_t)row*1024 + t*4) >> 1;
    __half2 pa, pb;
    pa.x=h0;pa.y=h1;pb.x=h2;pb.y=h3; ((__half2*)yh)[oi]=pa; ((__half2*)yh)[oi+1]=pb;
    pa.x=l0;pa.y=l1;pb.x=l2;pb.y=l3; ((__half2*)yl)[oi]=pa; ((__half2*)yl)[oi+1]=pb;
}

// ---- fp16x2 GEMM: A split (hi/lo), B single; 3-stage, 2 CTAs/SM ----
#define ATILE_B  10240
#define STAGE_H  30720
#define GSMEM_H  (3*STAGE_H)

__device__ __forceinline__ void issue_stage_h(
    const __half* __restrict__ Ah, const __half* __restrict__ Al,
    const __half* __restrict__ Bs,
    uint32_t sbase, int bm, int bn, int ko, int K, int tid)
{
    #pragma unroll
    for (int i = 0; i < 6; ++i) {
        int lin = tid + (i << 8);
        int tile = lin >> 9;
        int wit = lin & 511;
        int r = wit >> 2, ch = wit & 3;
        const __half* gp;
        if      (tile == 0) gp = Ah + (size_t)(bm + r) * K + ko + ch*8;
        else if (tile == 1) gp = Al + (size_t)(bm + r) * K + ko + ch*8;
        else                gp = Bs + (size_t)(bn + r) * K + ko + ch*8;
        CP_ASYNC16(sbase + tile*ATILE_B + r*80 + ch*16, gp);
    }
    CP_COMMIT();
}

// EPI 0: QKV scatter(+bias) | 1: +bias+res->outf | 2: split(relu·mask) | 3: res+acc·mask
template<int EPI>
__global__ void __launch_bounds__(256, 2)
tc_gemm16(const __half* __restrict__ Ah, const __half* __restrict__ Al,
          const __half* __restrict__ Bs,
          const float* __restrict__ bias, const float* __restrict__ aux,
          const float* __restrict__ res, float* __restrict__ outf,
          __half* __restrict__ outh, __half* __restrict__ outl, int N, int K)
{
    extern __shared__ char smem[];
    uint32_t sb = s2u(smem);
    const int tid = threadIdx.x, lane = tid & 31, wid = tid >> 5;
    const int wm = wid & 3, wn = wid >> 2;
    const int bm = blockIdx.y << 7, bn = blockIdx.x << 7;

    float acc[2][8][4];
    #pragma unroll
    for (int i = 0; i < 2; ++i)
        #pragma unroll
        for (int j = 0; j < 8; ++j)
            #pragma unroll
            for (int q = 0; q < 4; ++q) acc[i][j][q] = 0.f;

    const int ktn = K >> 5;
    issue_stage_h(Ah, Al, Bs, sb, bm, bn, 0, K, tid);
    if (ktn > 1) issue_stage_h(Ah, Al, Bs, sb + STAGE_H, bm, bn, 32, K, tid);

    const int a_ro = (lane & 15);
    const int a_ko = (lane >> 4) * 8;
    const int b_rp = ((lane >> 4) & 1) * 8 + (lane & 7);
    const int b_ko = ((lane >> 3) & 1) * 8;

    for (int kt = 0; kt < ktn; ++kt) {
        if (kt + 1 < ktn) CP_WAIT1(); else CP_WAIT0();
        __syncthreads();
        if (kt + 2 < ktn)
            issue_stage_h(Ah, Al, Bs, sb + ((kt + 2) % 3) * STAGE_H,
                          bm, bn, (kt + 2) * 32, K, tid);
        uint32_t st = sb + (kt % 3) * STAGE_H;
        #pragma unroll
        for (int ks = 0; ks < 2; ++ks) {
            uint32_t ahi[2][4], alo[2][4], bfr[4][4];
            #pragma unroll
            for (int mf = 0; mf < 2; ++mf) {
                uint32_t ad = st + (wm*32 + mf*16 + a_ro)*80 + (ks*16 + a_ko)*2;
                ldsm4(ahi[mf], ad);
                ldsm4(alo[mf], ad + ATILE_B);
            }
            #pragma unroll
            for (int np = 0; np < 4; ++np)
                ldsm4(bfr[np], st + 2*ATILE_B + (wn*64 + np*16 + b_rp)*80 + (ks*16 + b_ko)*2);
            #pragma unroll
            for (int np = 0; np < 4; ++np)
                #pragma unroll
                for (int mf = 0; mf < 2; ++mf) {
                    mma16816h(acc[mf][np*2  ], ahi[mf], &bfr[np][0]);
                    mma16816h(acc[mf][np*2+1], ahi[mf], &bfr[np][2]);
                }
            #pragma unroll
            for (int np = 0; np < 4; ++np)
                #pragma unroll
                for (int mf = 0; mf < 2; ++mf) {
                    mma16816h(acc[mf][np*2  ], alo[mf], &bfr[np][0]);
                    mma16816h(acc[mf][np*2+1], alo[mf], &bfr[np][2]);
                }
        }
    }

    const int tr = lane >> 2;
    const int tc = (lane & 3) * 2;
    #pragma unroll
    for (int mf = 0; mf < 2; ++mf) {
        #pragma unroll
        for (int nf = 0; nf < 8; ++nf) {
            int gj = bn + wn*64 + nf*8 + tc;
            float2 b2 = *(const float2*)&bias[gj];
            #pragma unroll
            for (int h = 0; h < 2; ++h) {
                int gi = bm + wm*32 + mf*16 + tr + h*8;
                float v0 = acc[mf][nf][h*2]   + b2.x;
                float v1 = acc[mf][nf][h*2+1] + b2.y;
                size_t off = (size_t)gi * N + gj;
                if (EPI == 0) {
                    int wh = gj >> 10, hh = (gj >> 6) & 15, d = gj & 63;
                    int bb = gi >> 10, nn = gi & 1023;
                    size_t idx = (((size_t)(bb*16 + hh))*1024 + nn)*64 + d;
                    if (wh == 0) {
                        __half h0,l0,h1,l1;
                        h16split(v0,h0,l0); h16split(v1,h1,l1);
                        __half2 ph, pl; ph.x=h0; ph.y=h1; pl.x=l0; pl.y=l1;
                        *(__half2*)&g_qh[idx] = ph; *(__half2*)&g_ql[idx] = pl;
                    } else if (wh == 1) {
                        *(__half2*)&g_k16[idx] = __floats2half2_rn(v0, v1);
                    } else {
                        *(__half2*)&g_v[idx] = __floats2half2_rn(v0, v1);
                    }
                } else if (EPI == 1) {
                    float2 rr = *(const float2*)&res[off];
                    float2 o; o.x = v0 + rr.x; o.y = v1 + rr.y;
                    *(float2*)&outf[off] = o;
                } else if (EPI == 2) {
                    float2 m = *(const float2*)&aux[off];
                    v0 = (m.x > 0.5f) ? fmaxf(v0, 0.f) : 0.f;
                    v1 = (m.y > 0.5f) ? fmaxf(v1, 0.f) : 0.f;
                    __half h0,l0,h1,l1;
                    h16split(v0,h0,l0); h16split(v1,h1,l1);
                    __half2 p; p.x=h0; p.y=h1; *(__half2*)&outh[off] = p;
                    p.x=l0; p.y=l1;            *(__half2*)&outl[off] = p;
                } else {
                    float2 m  = *(const float2*)&aux[off];
                    float2 rr = *(const float2*)&res[off];
                    float2 o;
                    o.x = rr.x + ((m.x > 0.5f) ? v0 : 0.f);
                    o.y = rr.y + ((m.y > 0.5f) ? v1 : 0.f);
                    *(float2*)&outf[off] = o;
                }
            }
        }
    }
}

// ------- sparse attention: 4-stage K ring, seeded search, scan compaction --
#define SS_STR  1034
#define SS_OFF  20736              /* (9216 + 4*18432)/4 */
#define ATTN_SMEM (9216 + 4*18432 + 32*SS_STR*4)

__device__ __forceinline__ void issue_k(uint32_t sb, size_t bhoff, int kt, int buf, int tid) {
    #pragma unroll
    for (int i = 0; i < 2; ++i) {
        int lin = tid + (i << 9);
        int r = lin >> 3, ch = lin & 7;
        const __half* gsrc = g_k16 + bhoff + (size_t)(kt*128 + r)*64 + ch*8;
        CP_ASYNC16(sb + 9216 + buf*18432 + r*144 + ch*16, gsrc);
    }
    CP_COMMIT();
}

__device__ __forceinline__ float dec(unsigned ub) {
    unsigned fb = ub ^ ((ub & 0x80000000u) ? 0x80000000u : 0xFFFFFFFFu);
    return __uint_as_float(fb);
}

__global__ void __launch_bounds__(512)
attn_kernel()
{
    extern __shared__ char smraw[];
    float* smf = (float*)smraw;
    uint32_t sb = s2u(smraw);

    int blk = blockIdx.x, bh = blk >> 5, n0 = (blk & 31) << 5;
    int tid = threadIdx.x, lane = tid & 31, w = tid >> 5;
    const size_t bhoff = (size_t)bh * 65536;

    {
        int tile = tid >> 8, wit = tid & 255, r = wit >> 3, ch = wit & 7;
        const __half* gsrc = (tile ? g_ql : g_qh) + bhoff + (size_t)(n0 + r)*64 + ch*8;
        *(uint4*)(smraw + tile*4608 + r*144 + ch*16) = *(const uint4*)gsrc;
    }
    // prologue: 3-deep K prefetch
    issue_k(sb, bhoff, 0, 0, tid);
    issue_k(sb, bhoff, 1, 1, tid);
    issue_k(sb, bhoff, 2, 2, tid);
    __syncthreads();

    const int wm = w & 1, wn = w >> 1;
    const int a_ro = lane & 15, a_ko = (lane >> 4) * 8;
    const int b_rp = ((lane >> 4) & 1) * 8 + (lane & 7);
    const int b_ko = ((lane >> 3) & 1) * 8;
    uint32_t qhi[4][4], qlo[4][4];
    #pragma unroll
    for (int ks = 0; ks < 4; ++ks) {
        uint32_t qa = sb + (wm*16 + a_ro)*144 + (ks*16 + a_ko)*2;
        ldsm4(qhi[ks], qa);
        ldsm4(qlo[ks], qa + 4608);
    }
    const int tr = lane >> 2, tc = (lane & 3) * 2;

    // ---- phase 1: scores via fp16 HMMA (4-buffer K ring, 3-deep prefetch) ----
    #pragma unroll
    for (int kt = 0; kt < 8; ++kt) {
        if (kt <= 5)      CP_WAIT2();
        else if (kt == 6) CP_WAIT1();
        else              CP_WAIT0();
        __syncthreads();
        if (kt + 3 < 8) issue_k(sb, bhoff, kt + 3, (kt + 3) & 3, tid);
        uint32_t kb = sb + 9216 + (kt & 3)*18432;
        float acc[2][4];
        #pragma unroll
        for (int nf = 0; nf < 2; ++nf)
            #pragma unroll
            for (int q = 0; q < 4; ++q) acc[nf][q] = 0.f;
        #pragma unroll
        for (int ks = 0; ks < 4; ++ks) {
            uint32_t bd = kb + (wn*16 + b_rp)*144 + (ks*16 + b_ko)*2;
            uint32_t bfr[4];
            ldsm4(bfr, bd);
            mma16816h(acc[0], qhi[ks], &bfr[0]);
            mma16816h(acc[1], qhi[ks], &bfr[2]);
            mma16816h(acc[0], qlo[ks], &bfr[0]);
            mma16816h(acc[1], qlo[ks], &bfr[2]);
        }
        #pragma unroll
        for (int nf = 0; nf < 2; ++nf) {
            int key = kt*128 + wn*16 + nf*8 + tc;
            int row0 = wm*16 + tr;
            float2 o;
            o.x = acc[nf][0]*0.125f; o.y = acc[nf][1]*0.125f;
            *(float2*)&smf[SS_OFF + row0*SS_STR + key] = o;
            o.x = acc[nf][2]*0.125f; o.y = acc[nf][3]*0.125f;
            *(float2*)&smf[SS_OFF + (row0+8)*SS_STR + key] = o;
        }
    }
    __syncthreads();

    // ---- per-row: seeded early-exit top-k, scan compaction, PV ----
    int r0 = 2 * w;
    float o00=0, o01=0, o10=0, o11=0;
    const __half* Vb = g_v + bhoff;
    #pragma unroll 1
    for (int rr = 0; rr < 2; ++rr) {
        float* srow = &smf[SS_OFF + (r0 + rr) * SS_STR];
        unsigned key[32];
        unsigned kmax = 0u, kmin = 0xFFFFFFFFu;
        #pragma unroll
        for (int i = 0; i < 32; ++i) {
            float s = srow[lane + 32*i];
            unsigned ub = __float_as_uint(s);
            unsigned k = ub ^ (((unsigned)((int)ub >> 31)) | 0x80000000u);
            key[i] = k;
            kmax = k > kmax ? k : kmax;
            kmin = k < kmin ? k : kmin;
        }
        kmax = __reduce_max_sync(~0u, kmax);
        kmin = __reduce_min_sync(~0u, kmin);
        float lmax = dec(kmax);

        unsigned T;
        {
            unsigned lo = kmin, hi = kmax;
            while (lo < hi) {
                unsigned mid = lo + (unsigned)(((unsigned long long)(hi - lo) + 1ull) >> 1);
                unsigned c = 0;
                #pragma unroll
                for (int i = 0; i < 32; ++i) c += (key[i] >= mid) ? 1u : 0u;
                c = __reduce_add_sync(~0u, c);
                if (c == (unsigned)KSP) { lo = mid; break; }
                if (c > (unsigned)KSP) lo = mid; else hi = mid - 1u;
            }
            T = lo;
        }

        unsigned selmask = 0u;
        #pragma unroll
        for (int i = 0; i < 32; ++i)
            if (key[i] >= T) selmask |= (1u << i);
        int c = __popc(selmask);

        int off = c;
        #pragma unroll
        for (int o = 1; o < 32; o <<= 1) {
            int nsh = __shfl_up_sync(~0u, off, o);
            if (lane >= o) off += nsh;
        }
        int total = __shfl_sync(~0u, off, 31);
        off -= c;
        int cnt = total > 128 ? 128 : total;

        uint2* lst = (uint2*)srow;
        float lsum = 0.f;
        unsigned m = selmask;
        while (m) {
            int i = __ffs(m) - 1;
            m &= m - 1u;
            float e = __expf(dec(key[i]) - lmax);
            lsum += e;
            if (off < 128) {
                uint2 en; en.x = __float_as_uint(e); en.y = (unsigned)(lane + 32*i);
                lst[off] = en;
            }
            ++off;
        }
        #pragma unroll
        for (int o = 16; o; o >>= 1) lsum += __shfl_xor_sync(~0u, lsum, o);
        float inv = 1.f / lsum;
        __syncwarp();

        float a0 = 0.f, a1 = 0.f;
        #pragma unroll 8
        for (int j = 0; j < cnt; ++j) {
            uint2 e = lst[j];
            float p = __uint_as_float(e.x);
            __half2 hv = __ldg((const __half2*)(Vb + (size_t)e.y * 64) + lane);
            float2 v = __half22float2(hv);
            a0 = fmaf(p, v.x, a0);
            a1 = fmaf(p, v.y, a1);
        }
        a0 *= inv;
        a1 *= inv;
        if (rr == 0) { o00 = a0; o01 = a1; } else { o10 = a0; o11 = a1; }
    }

    int bb = bh >> 4, hh = bh & 15;
    {
        size_t base0 = ((size_t)(bb*1024 + n0 + r0    )) * 1024 + hh*64 + lane*2;
        size_t base1 = ((size_t)(bb*1024 + n0 + r0 + 1)) * 1024 + hh*64 + lane*2;
        __half h0, l0, h1, l1;
        h16split(o00, h0, l0); h16split(o01, h1, l1);
        __half2 ph, pl; ph.x = h0; ph.y = h1; pl.x = l0; pl.y = l1;
        *(__half2*)&g_ath[base0] = ph; *(__half2*)&g_atl[base0] = pl;
        h16split(o10, h0, l0); h16split(o11, h1, l1);
        ph.x = h0; ph.y = h1; pl.x = l0; pl.y = l1;
        *(__half2*)&g_ath[base1] = ph; *(__half2*)&g_atl[base1] = pl;
    }
}

// ---------------- launch ----------------
extern "C" void kernel_launch(void* const* d_in, const int* in_sizes, int n_in,
                              void* d_out, int out_size)
{
    (void)in_sizes; (void)n_in; (void)out_size;
    const float* x     = (const float*)d_in[0];
    const float* ln1_w = (const float*)d_in[1];
    const float* ln1_b = (const float*)d_in[2];
    const float* qkv_w = (const float*)d_in[3];
    const float* qkv_b = (const float*)d_in[4];
    const float* out_w = (const float*)d_in[5];
    const float* out_b = (const float*)d_in[6];
    const float* ln2_w = (const float*)d_in[7];
    const float* ln2_b = (const float*)d_in[8];
    const float* w1    = (const float*)d_in[9];
    const float* b1    = (const float*)d_in[10];
    const float* w2    = (const float*)d_in[11];
    const float* b2    = (const float*)d_in[12];
    const float* mask1 = (const float*)d_in[13];
    const float* mask2 = (const float*)d_in[14];
    float* out = (float*)d_out;

    void *x1, *xnh, *xnl, *hnh, *hnl, *ath, *atl, *h1h, *h1l,
         *qw16, *ow16, *w116, *w216;
    cudaGetSymbolAddress(&x1, g_x1);
    cudaGetSymbolAddress(&xnh, g_xnh); cudaGetSymbolAddress(&xnl, g_xnl);
    cudaGetSymbolAddress(&hnh, g_hnh); cudaGetSymbolAddress(&hnl, g_hnl);
    cudaGetSymbolAddress(&ath, g_ath); cudaGetSymbolAddress(&atl, g_atl);
    cudaGetSymbolAddress(&h1h, g_h1h); cudaGetSymbolAddress(&h1l, g_h1l);
    cudaGetSymbolAddress(&qw16, g_qw16);
    cudaGetSymbolAddress(&ow16, g_ow16);
    cudaGetSymbolAddress(&w116, g_w116);
    cudaGetSymbolAddress(&w216, g_w216);

    cudaFuncSetAttribute(attn_kernel, cudaFuncAttributeMaxDynamicSharedMemorySize, ATTN_SMEM);
    cudaFuncSetAttribute(tc_gemm16<0>, cudaFuncAttributeMaxDynamicSharedMemorySize, GSMEM_H);
    cudaFuncSetAttribute(tc_gemm16<1>, cudaFuncAttributeMaxDynamicSharedMemorySize, GSMEM_H);
    cudaFuncSetAttribute(tc_gemm16<2>, cudaFuncAttributeMaxDynamicSharedMemorySize, GSMEM_H);
    cudaFuncSetAttribute(tc_gemm16<3>, cudaFuncAttributeMaxDynamicSharedMemorySize, GSMEM_H);

    // order: [0]cvt [1]cvt [2]ln1 [3]gemm0 [4]attn
    cvt_w2<<<4096, 256>>>(qkv_w, (__half*)qw16, 786432,
                          out_w, (__half*)ow16, 262144);
    cvt_w2<<<8192, 256>>>(w1, (__half*)w116, 1048576,
                          w2, (__half*)w216, 1048576);

    ln_f16<<<M_, 256>>>(x, ln1_w, ln1_b, (__half*)xnh, (__half*)xnl);

    tc_gemm16<0><<<dim3(24, 64), 256, GSMEM_H>>>((__half*)xnh, (__half*)xnl,
        (__half*)qw16, qkv_b, nullptr, nullptr, nullptr, nullptr, nullptr, 3*C_, C_);

    attn_kernel<<<BH_*(N_/32), 512, ATTN_SMEM>>>();

    tc_gemm16<1><<<dim3(8, 64), 256, GSMEM_H>>>((__half*)ath, (__half*)atl,
        (__half*)ow16, out_b, nullptr, x, (float*)x1, nullptr, nullptr, C_, C_);

    ln_f16<<<M_, 256>>>((float*)x1, ln2_w, ln2_b, (__half*)hnh, (__half*)hnl);

    tc_gemm16<2><<<dim3(32, 64), 256, GSMEM_H>>>((__half*)hnh, (__half*)hnl,
        (__half*)w116, b1, mask1, nullptr, nullptr, (__half*)h1h, (__half*)h1l, FF_, C_);

    tc_gemm16<3><<<dim3(8, 64), 256, GSMEM_H>>>((__half*)h1h, (__half*)h1l,
        (__half*)w216, b2, mask2, (float*)x1, out, nullptr, nullptr, C_, FF_);
}